// round 11
// baseline (speedup 1.0000x reference)
#include <cuda_runtime.h>
#include <cstdint>

#define MBLK    64
#define PDIM    256
#define ROWLEN  16384
#define KTOT    768
#define NIT     12            // iterations (64-K each)
#define STAGES  2
#define STAGE_BYTES 98304     // [A0 16K][A1 16K][B0 32K][B1 32K]
#define SMEM_BYTES  (STAGES * STAGE_BYTES)   // 196608 -> 1 CTA/SM
#define THREADS 256

// repacked weights [i][q][768], tf32-rounded, truncation-compensated,
// k-permuted within 8-groups as [0,4,1,5,2,6,3,7] for LDS.64 fragments
__device__ float g_w[(size_t)MBLK * PDIM * KTOT];

// ---------- weight repack ----------
__global__ void cvt_w_kernel(const float* __restrict__ Wd,
                             const float* __restrict__ Wu,
                             const float* __restrict__ Wl,
                             const float* __restrict__ Wtr,
                             const float* __restrict__ Wbl) {
    size_t idx = (size_t)blockIdx.x * blockDim.x + threadIdx.x;
    size_t total = (size_t)MBLK * PDIM * KTOT;
    if (idx >= total) return;
    int i = (int)(idx / ((size_t)PDIM * KTOT));
    int r = (int)(idx % ((size_t)PDIM * KTOT));
    int q = r / KTOT;
    int kp = r % KTOT;                 // permuted position
    int p  = kp & 7;
    int k  = (kp & ~7) + (p >> 1) + ((p & 1) << 2);   // actual k
    int seg = k >> 8;
    int pp = k & 255;
    float v;
    if (seg == 0) {
        v = (i == 0) ? Wtr[q * PDIM + pp]
                     : Wl[(size_t)(i - 1) * PDIM * PDIM + q * PDIM + pp];
    } else if (seg == 1) {
        v = Wd[(size_t)i * PDIM * PDIM + q * PDIM + pp];
    } else {
        v = (i == MBLK - 1) ? Wbl[q * PDIM + pp]
                            : Wu[(size_t)i * PDIM * PDIM + q * PDIM + pp];
    }
    // compensate mean tf32 truncation of raw-fp32 A operand (2^-11)
    v *= 1.00048828125f;
    uint32_t u;
    asm("cvt.rna.tf32.f32 %0, %1;" : "=r"(u) : "f"(v));
    g_w[idx] = __uint_as_float(u);
}

// ---------- tf32 legacy-HMMA GEMM ----------
// Grid (32 mb, 64 i), 256 threads, CTA tile 128x256x64,
// 8 warps 2x4 (warp tile 64x64), 2-stage ring of 96KB stages
// (each = 2 old-style 32-K sub-tiles), XOR swizzle, 1 CTA/SM.
// 12 iterations -> half the barriers; A gmem traffic halved vs BN=128.
__global__ void __launch_bounds__(THREADS, 1)
bxd_gemm(const float* __restrict__ x, float* __restrict__ out) {
    extern __shared__ char smem[];
    uint32_t sbase;
    asm("{ .reg .u64 t; cvta.to.shared.u64 t, %1; cvt.u32.u64 %0, t; }"
        : "=r"(sbase) : "l"(smem));

    const int tid = threadIdx.x;
    const int mb = blockIdx.x;   // batch tile 0..31
    const int i  = blockIdx.y;   // block row 0..63

    const int warp = tid >> 5, lane = tid & 31;
    const int wr = warp >> 2, wc = warp & 3;   // 2x4 warp grid
    const int g  = lane >> 2, tg = lane & 3;

    int jcol[3];
    jcol[0] = (i + MBLK - 1) & (MBLK - 1);
    jcol[1] = i;
    jcol[2] = (i + 1) & (MBLK - 1);

    // ---- cp.async lanes: lrow 0..31, 16B chunk lk4 0..7
    const int lrow = tid >> 3;
    const int lk4  = tid & 7;
    const int chk  = ((lk4 ^ (lrow & 7)) << 4);
    const float* gA = x + (size_t)(mb * 128 + lrow) * ROWLEN + lk4 * 4;
    const float* gB = g_w + (size_t)(i * 256 + lrow) * KTOT + lk4 * 4;
    const uint32_t sA = sbase + lrow * 128 + chk;   // + half*16384
    const uint32_t sB = sA + 32768;                 // + half*32768

    // ---- fragment read byte offsets (within sub-tile)
    uint32_t aRow[4][2], bRow[8];
#pragma unroll
    for (int mf = 0; mf < 4; mf++) {
        aRow[mf][0] = (wr * 64 + mf * 16 + g) * 128 + tg * 4;
        aRow[mf][1] = aRow[mf][0] + 8 * 128;
    }
#pragma unroll
    for (int nf = 0; nf < 8; nf++)
        bRow[nf] = 32768 + (wc * 64 + nf * 8 + g) * 128 + (tg & 1) * 8;

    float acc[4][8][4];
#pragma unroll
    for (int mf = 0; mf < 4; mf++)
#pragma unroll
        for (int nf = 0; nf < 8; nf++)
#pragma unroll
            for (int c = 0; c < 4; c++) acc[mf][nf][c] = 0.0f;

    uint32_t a[2][4][4], b[2][8][2];

    // u = old-style 32-K tile index 0..23; stage s=(u>>1)&1, half=u&1
    auto issue_A = [&](int u) {
        const uint32_t st = ((u >> 1) & 1) * STAGE_BYTES + (u & 1) * 16384;
        const float* a0 = gA + jcol[u >> 3] * PDIM + (u & 7) * 32;
#pragma unroll
        for (int t = 0; t < 4; t++)
            asm volatile("cp.async.cg.shared.global [%0], [%1], 16;"
                         :: "r"(sA + st + t * 32 * 128),
                            "l"(a0 + (size_t)t * 32 * ROWLEN));
    };
    auto issue_B = [&](int u) {
        const uint32_t st = ((u >> 1) & 1) * STAGE_BYTES + (u & 1) * 32768;
        const float* b0 = gB + u * 32;
#pragma unroll
        for (int t = 0; t < 8; t++)
            asm volatile("cp.async.cg.shared.global [%0], [%1], 16;"
                         :: "r"(sB + st + t * 32 * 128),
                            "l"(b0 + (size_t)t * 32 * KTOT));
    };

    auto load_frags = [&](uint32_t stg, int ks, int buf) {
        const uint32_t stA2 = stg + (ks >> 2) * 16384;
        const uint32_t stB2 = stg + (ks >> 2) * 32768;
        const int ksl = ks & 3;
        const uint32_t c0 = (((2 * ksl) ^ g) << 4);
        const uint32_t c1 = (((2 * ksl + 1) ^ g) << 4);
        // A: raw fp32 bits (HW truncates to tf32; compensated in W)
#pragma unroll
        for (int mf = 0; mf < 4; mf++) {
            asm volatile("ld.shared.b32 %0, [%1];" : "=r"(a[buf][mf][0]) : "r"(stA2 + aRow[mf][0] + c0));
            asm volatile("ld.shared.b32 %0, [%1];" : "=r"(a[buf][mf][1]) : "r"(stA2 + aRow[mf][1] + c0));
            asm volatile("ld.shared.b32 %0, [%1];" : "=r"(a[buf][mf][2]) : "r"(stA2 + aRow[mf][0] + c1));
            asm volatile("ld.shared.b32 %0, [%1];" : "=r"(a[buf][mf][3]) : "r"(stA2 + aRow[mf][1] + c1));
        }
        // B: one LDS.64 per nf (k-permuted layout: {k=tg, k=tg+4} contiguous)
        const uint32_t bc = (((2 * ksl + (tg >> 1)) ^ g) << 4);
#pragma unroll
        for (int nf = 0; nf < 8; nf++)
            asm volatile("ld.shared.v2.b32 {%0, %1}, [%2];"
                         : "=r"(b[buf][nf][0]), "=r"(b[buf][nf][1])
                         : "r"(stB2 + bRow[nf] + bc));
    };

    issue_A(0); issue_B(0); issue_A(1); issue_B(1);
    asm volatile("cp.async.commit_group;");

    for (int kt = 0; kt < NIT; kt++) {
        asm volatile("cp.async.wait_group 0;");
        __syncthreads();

        const uint32_t stg = sbase + (kt & 1) * STAGE_BYTES;
        const bool pre = (kt + 1 < NIT);
        const int un = 2 * kt + 2;   // next iteration's first unit

        load_frags(stg, 0, 0);
#pragma unroll
        for (int ks = 0; ks < 8; ks++) {
            // spread next-iteration global loads under tensor-busy windows
            if (pre) {
                if (ks == 1) issue_A(un);
                if (ks == 2) issue_B(un);
                if (ks == 4) issue_A(un + 1);
                if (ks == 5) issue_B(un + 1);
            }
            if (ks < 7) load_frags(stg, ks + 1, (ks + 1) & 1);
            const int cur = ks & 1;
#pragma unroll
            for (int mf = 0; mf < 4; mf++)
#pragma unroll
                for (int nf = 0; nf < 8; nf++) {
                    float* c = acc[mf][nf];
                    asm volatile(
                        "mma.sync.aligned.m16n8k8.row.col.f32.tf32.tf32.f32 "
                        "{%0,%1,%2,%3}, {%4,%5,%6,%7}, {%8,%9}, {%0,%1,%2,%3};\n"
                        : "+f"(c[0]), "+f"(c[1]), "+f"(c[2]), "+f"(c[3])
                        : "r"(a[cur][mf][0]), "r"(a[cur][mf][1]),
                          "r"(a[cur][mf][2]), "r"(a[cur][mf][3]),
                          "r"(b[cur][nf][0]), "r"(b[cur][nf][1]));
                }
        }
        asm volatile("cp.async.commit_group;");
    }

    // epilogue: direct float2 stores (fragment layout (g, 2tg))
    size_t obase = (size_t)(mb * 128 + wr * 64) * ROWLEN
                 + (size_t)i * PDIM + wc * 64;
#pragma unroll
    for (int mf = 0; mf < 4; mf++) {
#pragma unroll
        for (int nf = 0; nf < 8; nf++) {
            int row = mf * 16 + g;
            int col = nf * 8 + tg * 2;
            float2 v0 = make_float2(acc[mf][nf][0], acc[mf][nf][1]);
            float2 v1 = make_float2(acc[mf][nf][2], acc[mf][nf][3]);
            *reinterpret_cast<float2*>(out + obase + (size_t)row * ROWLEN + col) = v0;
            *reinterpret_cast<float2*>(out + obase + (size_t)(row + 8) * ROWLEN + col) = v1;
        }
    }
}

// ---------------- launcher ----------------
extern "C" void kernel_launch(void* const* d_in, const int* in_sizes, int n_in,
                              void* d_out, int out_size) {
    const float* x   = (const float*)d_in[0];
    const float* Wd  = (const float*)d_in[1];
    const float* Wu  = (const float*)d_in[2];
    const float* Wl  = (const float*)d_in[3];
    const float* Wtr = (const float*)d_in[4];
    const float* Wbl = (const float*)d_in[5];
    float* out = (float*)d_out;

    cvt_w_kernel<<<49152, 256>>>(Wd, Wu, Wl, Wtr, Wbl);

    (void)cudaFuncSetAttribute(bxd_gemm,
                               cudaFuncAttributeMaxDynamicSharedMemorySize,
                               SMEM_BYTES);
    bxd_gemm<<<dim3(32, 64), THREADS, SMEM_BYTES>>>(x, out);
}